// round 15
// baseline (speedup 1.0000x reference)
#include <cuda_runtime.h>
#include <cuda_fp16.h>
#include <math.h>

// ---------------------------------------------------------------------------
// Fused causal MHA forward — plain-fp16 mma.sync, ldmatrix fragment loads.
//   GEMMs: 128x256 CTA tile, 512 thr, k64 stages, 3-stage cp.async ring.
//   Flash: round-14 (ex2.f16x2 softmax, ones-column sums, rescale-skip).
// ---------------------------------------------------------------------------

#define SEQ   4096
#define BATCH 2
#define DM    2048
#define NH    16
#define DH    128
#define ROWS  (BATCH * SEQ)      // 8192
#define WU    (DM * DM / 2)      // u32 per packed weight plane
#define RWU   (DM / 2)           // u32 per packed activation row

__device__ float    g_cos[SEQ * 64];
__device__ float    g_sin[SEQ * 64];
__device__ unsigned g_xs[ROWS * RWU];       // x plain fp16
__device__ unsigned g_as[ROWS * RWU];       // attn out plain fp16
__device__ unsigned g_ws[4 * WU];           // Wq|Wk|Wv|Wo plain fp16
__device__ unsigned g_qs1[ROWS * 1024];     // Q rope+scale, plain fp16
__device__ unsigned g_ks1[ROWS * 1024];     // K rope, plain fp16
__device__ unsigned g_v1[ROWS * 1024];      // V plain fp16 plane

// ---------------------------------------------------------------------------
__device__ __forceinline__ void mma_f16(float4& c,
                                        unsigned a0, unsigned a1, unsigned a2, unsigned a3,
                                        unsigned b0, unsigned b1) {
    asm("mma.sync.aligned.m16n8k16.row.col.f32.f16.f16.f32 "
        "{%0,%1,%2,%3}, {%4,%5,%6,%7}, {%8,%9}, {%0,%1,%2,%3};"
        : "+f"(c.x), "+f"(c.y), "+f"(c.z), "+f"(c.w)
        : "r"(a0), "r"(a1), "r"(a2), "r"(a3), "r"(b0), "r"(b1));
}

__device__ __forceinline__ void ldsm_x4(uint4& r, unsigned addr) {
    asm volatile("ldmatrix.sync.aligned.m8n8.x4.shared.b16 {%0,%1,%2,%3}, [%4];"
                 : "=r"(r.x), "=r"(r.y), "=r"(r.z), "=r"(r.w) : "r"(addr));
}

__device__ __forceinline__ void ldsm_x4t(uint4& r, unsigned addr) {
    asm volatile("ldmatrix.sync.aligned.m8n8.x4.trans.shared.b16 {%0,%1,%2,%3}, [%4];"
                 : "=r"(r.x), "=r"(r.y), "=r"(r.z), "=r"(r.w) : "r"(addr));
}

__device__ __forceinline__ unsigned pack_f16x2(float x, float y) {
    __half2 h = __floats2half2_rn(x, y);
    return *(unsigned*)&h;
}

__device__ __forceinline__ unsigned ex2_f16x2(unsigned a) {
    unsigned r;
    asm("ex2.approx.f16x2 %0, %1;" : "=r"(r) : "r"(a));
    return r;
}

// ---------------------------------------------------------------------------
__global__ void rope_tables_kernel() {
    int idx = blockIdx.x * blockDim.x + threadIdx.x;
    int s = idx >> 6, i = idx & 63;
    double invd = pow(10000.0, -((double)(2 * i)) / 128.0);
    float arg = (float)s * (float)invd;
    double sv, cv;
    sincos((double)arg, &sv, &cv);
    g_cos[idx] = (float)cv;
    g_sin[idx] = (float)sv;
}

// One launch packs x + all four weights to fp16.
__global__ void packall_kernel(const float* __restrict__ x,
                               const float* __restrict__ Wq,
                               const float* __restrict__ Wk,
                               const float* __restrict__ Wv,
                               const float* __restrict__ Wo,
                               unsigned* __restrict__ xs,
                               unsigned* __restrict__ ws) {
    int p = blockIdx.x * blockDim.x + threadIdx.x;
    const int XP = ROWS * RWU;
    const float* src;
    unsigned* dst;
    int off;
    if (p < XP) {
        src = x; dst = xs; off = p;
    } else {
        int q = p - XP;
        int wsel = q >> 21;
        off = q & (WU - 1);
        src = (wsel == 0) ? Wq : (wsel == 1) ? Wk : (wsel == 2) ? Wv : Wo;
        dst = ws + wsel * WU;
    }
    float2 v = *(const float2*)&src[2 * off];
    dst[off] = pack_f16x2(v.x, v.y);
}

// ---------------------------------------------------------------------------
// GEMM C[m,n] = sum_k A[m,k]*B[n,k]. Plain fp16, ldmatrix, k64 stages.
// 128m x 256n CTA tile, 512 thr (16 warps, 2x8), warp 64x32, 3-stage ring.
// modes: 0 = fp32 C; -1 = per bx>>3: 0->Q(rope+scale), 1->K(rope), 2->V.
// ---------------------------------------------------------------------------
#define MG_A_U    4608                        // 128 rows x 36 u32
#define MG_B_U    9216                        // 256 rows x 36 u32
#define MG_STAGEU (MG_A_U + MG_B_U)           // 13824 u32 = 55296 B
#define MG_SMEM_BYTES (3 * MG_STAGEU * 4)     // 165888
#define MG_KT     (DM / 64)                   // 32

__global__ __launch_bounds__(512, 1) void mgemm_h1(
        const unsigned* __restrict__ Ag, const unsigned* __restrict__ Bg,
        int modes, float* __restrict__ Cf,
        unsigned* __restrict__ Pv,
        unsigned* __restrict__ Pq, unsigned* __restrict__ Pk) {
    extern __shared__ unsigned sm[];
    const unsigned sbase = (unsigned)__cvta_generic_to_shared(sm);
    const int tid = threadIdx.x, wid = tid >> 5, lane = tid & 31;
    const int wm = wid >> 3, wn = wid & 7, g8 = lane >> 2, qd = lane & 3;
    const int bx = blockIdx.x, by = blockIdx.y;

    // loaders: A 1024 chunks (2/thread), B 2048 chunks (4/thread)
    const int lrA = tid >> 3, lcA = (tid & 7) << 2;
    const unsigned* sA = Ag + (size_t)(by * 128 + lrA) * RWU + lcA;
    const unsigned dA0 = sbase + (unsigned)(lrA * 36 + lcA) * 4u;
    const unsigned* sB = Bg + (size_t)(bx * 256 + lrA) * RWU + lcA;
    const unsigned dB0 = sbase + (unsigned)(MG_A_U + lrA * 36 + lcA) * 4u;

    auto load_stage = [&](unsigned bufB, int kt) {
        const unsigned* a = sA + kt * 32;
#pragma unroll
        for (int l = 0; l < 2; ++l)
            asm volatile("cp.async.cg.shared.global [%0], [%1], 16;"
                         :: "r"(dA0 + bufB + (unsigned)(l * 2304 * 4)),
                            "l"(a + (size_t)l * 64 * RWU));
        const unsigned* b = sB + kt * 32;
#pragma unroll
        for (int l = 0; l < 4; ++l)
            asm volatile("cp.async.cg.shared.global [%0], [%1], 16;"
                         :: "r"(dB0 + bufB + (unsigned)(l * 2304 * 4)),
                            "l"(b + (size_t)l * 64 * RWU));
        asm volatile("cp.async.commit_group;");
    };

    float4 acc[4][4];
#pragma unroll
    for (int i = 0; i < 4; i++)
#pragma unroll
        for (int j = 0; j < 4; j++) acc[i][j] = make_float4(0.f, 0.f, 0.f, 0.f);

    const int lrow16 = lane & 15, lkh = lane >> 4;
    const unsigned aLd0 = sbase
        + (unsigned)(((wm * 64 + lrow16) * 36 + lkh * 4) * 4);
    const int bg = lane >> 3, brow = lane & 7;
    const unsigned bLd0 = sbase
        + (unsigned)((MG_A_U + (wn * 32 + (bg >> 1) * 8 + brow) * 36 + (bg & 1) * 4) * 4);

    auto compute = [&](unsigned so) {
#pragma unroll
        for (int ks = 0; ks < 4; ++ks) {
            uint4 af[4];
#pragma unroll
            for (int mi = 0; mi < 4; ++mi)
                ldsm_x4(af[mi], aLd0 + so + (unsigned)((mi * 576 + ks * 8) * 4));
            uint4 bf[2];
#pragma unroll
            for (int np = 0; np < 2; ++np)
                ldsm_x4(bf[np], bLd0 + so + (unsigned)((np * 576 + ks * 8) * 4));
#pragma unroll
            for (int mi = 0; mi < 4; ++mi) {
                mma_f16(acc[mi][0], af[mi].x, af[mi].y, af[mi].z, af[mi].w,
                        bf[0].x, bf[0].y);
                mma_f16(acc[mi][1], af[mi].x, af[mi].y, af[mi].z, af[mi].w,
                        bf[0].z, bf[0].w);
                mma_f16(acc[mi][2], af[mi].x, af[mi].y, af[mi].z, af[mi].w,
                        bf[1].x, bf[1].y);
                mma_f16(acc[mi][3], af[mi].x, af[mi].y, af[mi].z, af[mi].w,
                        bf[1].z, bf[1].w);
            }
        }
    };

    load_stage(0, 0);
    load_stage(MG_STAGEU * 4u, 1);
    int cs = 0, ls = 2;
#pragma unroll 1
    for (int kt = 0; kt < MG_KT; ++kt) {
        if (kt + 1 < MG_KT) asm volatile("cp.async.wait_group 1;");
        else                asm volatile("cp.async.wait_group 0;");
        __syncthreads();
        if (kt + 2 < MG_KT) {
            load_stage((unsigned)(ls * MG_STAGEU) * 4u, kt + 2);
            ls = (ls == 2) ? 0 : ls + 1;
        }
        compute((unsigned)(cs * MG_STAGEU) * 4u);
        cs = (cs == 2) ? 0 : cs + 1;
    }

    int mode, bxl;
    if (modes >= 0) { mode = modes; bxl = bx; }
    else { int r = bx >> 3; mode = (r == 0) ? 2 : (r == 1 ? 3 : 1); bxl = bx & 7; }
    const float SC = 0.08838834764831845f;   // 1/sqrt(128)

#pragma unroll
    for (int mi = 0; mi < 4; ++mi)
#pragma unroll
        for (int ni = 0; ni < 4; ++ni) {
            int r0 = by * 128 + wm * 64 + mi * 16 + g8;
            int c0 = bxl * 256 + wn * 32 + ni * 8 + 2 * qd;
            float4 v = acc[mi][ni];
            if (mode == 0) {
                *(float2*)&Cf[(size_t)r0 * DM + c0] = make_float2(v.x, v.y);
                *(float2*)&Cf[(size_t)(r0 + 8) * DM + c0] = make_float2(v.z, v.w);
            } else if (mode == 1) {        // V plain fp16 plane
                int pA = r0 * 1024 + (c0 >> 1);
                Pv[pA] = pack_f16x2(v.x, v.y);
                Pv[pA + 8192] = pack_f16x2(v.z, v.w);
            } else {                        // Q/K: rope (+scale), plain fp16
                int i = (c0 & 127) >> 1;
                int s0 = r0 & (SEQ - 1);
                float c_ = g_cos[(s0 << 6) + i], sn = g_sin[(s0 << 6) + i];
                float c1 = g_cos[((s0 + 8) << 6) + i], s1 = g_sin[((s0 + 8) << 6) + i];
                float x0 = v.x * c_ - v.y * sn, y0 = v.y * c_ + v.x * sn;
                float x1 = v.z * c1 - v.w * s1, y1 = v.w * c1 + v.z * s1;
                int pA = r0 * 1024 + (c0 >> 1);
                if (mode == 2) {
                    x0 *= SC; y0 *= SC; x1 *= SC; y1 *= SC;
                    Pq[pA] = pack_f16x2(x0, y0);
                    Pq[pA + 8192] = pack_f16x2(x1, y1);
                } else {
                    Pk[pA] = pack_f16x2(x0, y0);
                    Pk[pA + 8192] = pack_f16x2(x1, y1);
                }
            }
        }
}

// ---------------------------------------------------------------------------
// Flash attention (round-14): 128 q-rows/CTA, 64-key tiles, plain fp16 QK+PV,
// ex2.f16x2 softmax, ones-column MMA row sums, rescale-skip, 2 CTAs/SM.
// ---------------------------------------------------------------------------
#define FL_Q_U     (128 * 68)                 // 8704 u32
#define FLK_U      (64 * 68)
#define FLV_U      (64 * 64)
#define FL_STAGE_U (FLK_U + FLV_U)            // 8448 u32
#define FL_SMEM_BYTES ((FL_Q_U + 2 * FL_STAGE_U) * 4)   // 102400

#define ONES_F16X2 0x3C003C00u

__global__ __launch_bounds__(256, 2) void flash_mma(const unsigned* __restrict__ qs1,
                                                    const unsigned* __restrict__ ks1,
                                                    const unsigned* __restrict__ v1,
                                                    unsigned* __restrict__ As1) {
    extern __shared__ unsigned su[];
    const unsigned sb  = (unsigned)__cvta_generic_to_shared(su);
    const unsigned QsB = sb;
    const unsigned St0 = sb + FL_Q_U * 4;

    const int tid = threadIdx.x, lane = tid & 31, w = tid >> 5;
    const int gr = lane >> 2, q4 = lane & 3;
    const int qi = (int)gridDim.x - 1 - (int)blockIdx.x;   // longest first
    const int bh = blockIdx.y;
    const int b = bh >> 4, h = bh & 15;
    const size_t qrow0 = (size_t)(b * SEQ + qi * 128);
    const int ktmax = 2 * qi + 1;
    const float L2E = 1.4426950408889634f;

    // Q tile
#pragma unroll
    for (int it = 0; it < 8; ++it) {
        int c = tid + it * 256;
        int r = c >> 4, ch = c & 15;
        const unsigned* src = qs1 + (qrow0 + r) * 1024 + h * 64 + ch * 4;
        unsigned dst = QsB + (unsigned)(r * 68 + ch * 4) * 4u;
        asm volatile("cp.async.cg.shared.global [%0], [%1], 16;" :: "r"(dst), "l"(src));
    }
    asm volatile("cp.async.commit_group;");

    auto load_kv = [&](int s, int kt) {
        const size_t krow0 = (size_t)(b * SEQ + kt * 64);
        const unsigned KB = St0 + (unsigned)(s * FL_STAGE_U) * 4u;
        const unsigned VB = KB + FLK_U * 4u;
#pragma unroll
        for (int it = 0; it < 4; ++it) {
            int c = tid + it * 256;
            int r = c >> 4, ch = c & 15;
            const unsigned* src = ks1 + (krow0 + r) * 1024 + h * 64 + ch * 4;
            asm volatile("cp.async.cg.shared.global [%0], [%1], 16;"
                         :: "r"(KB + (unsigned)(r * 68 + ch * 4) * 4u), "l"(src));
        }
#pragma unroll
        for (int it = 0; it < 4; ++it) {
            int c = tid + it * 256;
            int s_ = c >> 4, cb = c & 15;
            unsigned soff = (unsigned)(s_ * 64 + ((cb ^ (s_ & 7)) << 2)) * 4u;
            const unsigned* src = v1 + (krow0 + s_) * 1024 + h * 64 + cb * 4;
            asm volatile("cp.async.cg.shared.global [%0], [%1], 16;"
                         :: "r"(VB + soff), "l"(src));
        }
        asm volatile("cp.async.commit_group;");
    };

    load_kv(0, 0);

    const int lrow16 = lane & 15, lkh = lane >> 4;
    const unsigned qLd0 = QsB + (unsigned)(((w * 16 + lrow16) * 68 + lkh * 4) * 4);
    const int bg = lane >> 3, brow = lane & 7;
    const unsigned kLdLane = (unsigned)((((bg >> 1) * 8 + brow) * 68 + (bg & 1) * 4) * 4);
    const int mgrp = lane >> 3, lr2 = lane & 7;

    float4 O[16];
#pragma unroll
    for (int j = 0; j < 16; ++j) O[j] = make_float4(0.f, 0.f, 0.f, 0.f);
    float4 Osum = make_float4(0.f, 0.f, 0.f, 0.f);
    float m0 = -INFINITY, m1 = -INFINITY;

    for (int kt = 0; kt <= ktmax; ++kt) {
        if (kt + 1 <= ktmax) {
            load_kv((kt + 1) & 1, kt + 1);
            asm volatile("cp.async.wait_group 1;");
        } else {
            asm volatile("cp.async.wait_group 0;");
        }
        __syncthreads();

        const int st = kt & 1;
        const unsigned KBb = St0 + (unsigned)(st * FL_STAGE_U) * 4u;
        const unsigned VB = KBb + FLK_U * 4u;

        float4 s4[8];
#pragma unroll
        for (int nt = 0; nt < 8; ++nt) s4[nt] = make_float4(0.f, 0.f, 0.f, 0.f);

#pragma unroll
        for (int t = 0; t < 8; ++t) {
            uint4 aq;
            ldsm_x4(aq, qLd0 + (unsigned)(t * 32));
            uint4 kf[4];
#pragma unroll
            for (int p = 0; p < 4; ++p)
                ldsm_x4(kf[p], KBb + kLdLane + (unsigned)(p * 4352 + t * 32));
#pragma unroll
            for (int p = 0; p < 4; ++p) {
                mma_f16(s4[2 * p],     aq.x, aq.y, aq.z, aq.w, kf[p].x, kf[p].y);
                mma_f16(s4[2 * p + 1], aq.x, aq.y, aq.z, aq.w, kf[p].z, kf[p].w);
            }
        }

        if (kt >= 2 * qi) {
            int off = (kt - 2 * qi) * 64;
            int r0 = w * 16 + gr, r1 = r0 + 8;
#pragma unroll
            for (int nt = 0; nt < 8; ++nt) {
                int c0 = nt * 8 + 2 * q4 + off;
                if (c0 > r0)     s4[nt].x = -INFINITY;
                if (c0 + 1 > r0) s4[nt].y = -INFINITY;
                if (c0 > r1)     s4[nt].z = -INFINITY;
                if (c0 + 1 > r1) s4[nt].w = -INFINITY;
            }
        }

        float mx0 = -INFINITY, mx1 = -INFINITY;
#pragma unroll
        for (int nt = 0; nt < 8; ++nt) {
            mx0 = fmaxf(mx0, fmaxf(s4[nt].x, s4[nt].y));
            mx1 = fmaxf(mx1, fmaxf(s4[nt].z, s4[nt].w));
        }
        mx0 = fmaxf(mx0, __shfl_xor_sync(0xffffffffu, mx0, 1));
        mx0 = fmaxf(mx0, __shfl_xor_sync(0xffffffffu, mx0, 2));
        mx1 = fmaxf(mx1, __shfl_xor_sync(0xffffffffu, mx1, 1));
        mx1 = fmaxf(mx1, __shfl_xor_sync(0xffffffffu, mx1, 2));
        float nm0 = fmaxf(m0, mx0), nm1 = fmaxf(m1, mx1);
        float al0 = __expf(m0 - nm0), al1 = __expf(m1 - nm1);
        m0 = nm0; m1 = nm1;

        unsigned need = __ballot_sync(0xffffffffu, (al0 < 1.f) | (al1 < 1.f));
        if (need) {
#pragma unroll
            for (int j = 0; j < 16; ++j) {
                O[j].x *= al0; O[j].y *= al0; O[j].z *= al1; O[j].w *= al1;
            }
            Osum.x *= al0; Osum.y *= al0; Osum.z *= al1; Osum.w *= al1;
        }

        const float nmL0 = nm0 * L2E, nmL1 = nm1 * L2E;
        unsigned phi[16];
#pragma unroll
        for (int nt = 0; nt < 8; ++nt) {
            unsigned lo = pack_f16x2(fmaf(s4[nt].x, L2E, -nmL0),
                                     fmaf(s4[nt].y, L2E, -nmL0));
            unsigned hi = pack_f16x2(fmaf(s4[nt].z, L2E, -nmL1),
                                     fmaf(s4[nt].w, L2E, -nmL1));
            phi[2 * nt]     = ex2_f16x2(lo);
            phi[2 * nt + 1] = ex2_f16x2(hi);
        }

#pragma unroll
        for (int t2 = 0; t2 < 4; ++t2) {
            unsigned pa0 = phi[4 * t2], pa1 = phi[4 * t2 + 1];
            unsigned pa2 = phi[4 * t2 + 2], pa3 = phi[4 * t2 + 3];
            const int srow = 16 * t2 + ((mgrp & 1) << 3) + lr2;
#pragma unroll
            for (int nh = 0; nh < 2; ++nh) {
                uint4 vf[4];
#pragma unroll
                for (int nb = 0; nb < 4; ++nb) {
                    int cb = 2 * (4 * nh + nb) + (mgrp >> 1);
                    unsigned off = (unsigned)(srow * 64 + ((cb ^ (srow & 7)) << 2)) * 4u;
                    ldsm_x4t(vf[nb], VB + off);
                }
#pragma unroll
                for (int nb = 0; nb < 4; ++nb) {
                    int j = 2 * (4 * nh + nb);
                    mma_f16(O[j],     pa0, pa1, pa2, pa3, vf[nb].x, vf[nb].y);
                    mma_f16(O[j + 1], pa0, pa1, pa2, pa3, vf[nb].z, vf[nb].w);
                }
            }
            mma_f16(Osum, pa0, pa1, pa2, pa3, ONES_F16X2, ONES_F16X2);
        }
        __syncthreads();
    }

    float inv0 = 1.0f / Osum.x, inv1 = 1.0f / Osum.z;
    size_t p0 = (qrow0 + w * 16 + gr) * RWU + h * 64;
    size_t p1 = p0 + (size_t)8 * RWU;
#pragma unroll
    for (int j = 0; j < 16; ++j) {
        int pc = j * 4 + q4;
        As1[p0 + pc] = pack_f16x2(O[j].x * inv0, O[j].y * inv0);
        As1[p1 + pc] = pack_f16x2(O[j].z * inv1, O[j].w * inv1);
    }
}

// ---------------------------------------------------------------------------
extern "C" void kernel_launch(void* const* d_in, const int* in_sizes, int n_in,
                              void* d_out, int out_size) {
    const float* x  = (const float*)d_in[0];
    const float* Wq = (const float*)d_in[1];
    const float* Wk = (const float*)d_in[2];
    const float* Wv = (const float*)d_in[3];
    const float* Wo = (const float*)d_in[4];
    float* out = (float*)d_out;

    unsigned *xs, *as, *ws, *v1, *ks1, *qs1;
    cudaGetSymbolAddress((void**)&xs, g_xs);
    cudaGetSymbolAddress((void**)&as, g_as);
    cudaGetSymbolAddress((void**)&ws, g_ws);
    cudaGetSymbolAddress((void**)&v1, g_v1);
    cudaGetSymbolAddress((void**)&ks1, g_ks1);
    cudaGetSymbolAddress((void**)&qs1, g_qs1);

    rope_tables_kernel<<<(SEQ * 64) / 256, 256>>>();

    const int TOTALP = ROWS * RWU + 4 * WU;
    packall_kernel<<<TOTALP / 256, 256>>>(x, Wq, Wk, Wv, Wo, xs, ws);

    cudaFuncSetAttribute(mgemm_h1, cudaFuncAttributeMaxDynamicSharedMemorySize,
                         MG_SMEM_BYTES);
    // QKV mega-GEMM: bx 0-7 -> Q, 8-15 -> K, 16-23 -> V  (N tile = 256)
    mgemm_h1<<<dim3(24, 64), 512, MG_SMEM_BYTES>>>(xs, ws, -1, nullptr,
                                                   v1, qs1, ks1);

    cudaFuncSetAttribute(flash_mma, cudaFuncAttributeMaxDynamicSharedMemorySize,
                         FL_SMEM_BYTES);
    flash_mma<<<dim3(SEQ / 128, BATCH * NH), 256, FL_SMEM_BYTES>>>(
        qs1, ks1, v1, as);

    mgemm_h1<<<dim3(8, 64), 512, MG_SMEM_BYTES>>>(as, ws + 3 * WU, 0, out,
                                                  nullptr, nullptr, nullptr);
}

// round 16
// speedup vs baseline: 1.1029x; 1.1029x over previous
#include <cuda_runtime.h>
#include <cuda_fp16.h>
#include <math.h>

// ---------------------------------------------------------------------------
// Fused causal MHA forward — plain-fp16 mma.sync, ldmatrix fragment loads.
//   GEMMs: 128x128 tile, 256 thr, k64 stages, 3-stage cp.async ring, 2 CTA/SM.
//   Flash: ex2.f16x2 softmax, ones-column MMA row sums, rescale-skip.
// ---------------------------------------------------------------------------

#define SEQ   4096
#define BATCH 2
#define DM    2048
#define NH    16
#define DH    128
#define ROWS  (BATCH * SEQ)      // 8192
#define WU    (DM * DM / 2)      // u32 per packed weight plane
#define RWU   (DM / 2)           // u32 per packed activation row

__device__ float    g_cos[SEQ * 64];
__device__ float    g_sin[SEQ * 64];
__device__ unsigned g_xs[ROWS * RWU];       // x plain fp16
__device__ unsigned g_as[ROWS * RWU];       // attn out plain fp16
__device__ unsigned g_ws[4 * WU];           // Wq|Wk|Wv|Wo plain fp16
__device__ unsigned g_qs1[ROWS * 1024];     // Q rope+scale, plain fp16
__device__ unsigned g_ks1[ROWS * 1024];     // K rope, plain fp16
__device__ unsigned g_v1[ROWS * 1024];      // V plain fp16 plane

// ---------------------------------------------------------------------------
__device__ __forceinline__ void mma_f16(float4& c,
                                        unsigned a0, unsigned a1, unsigned a2, unsigned a3,
                                        unsigned b0, unsigned b1) {
    asm("mma.sync.aligned.m16n8k16.row.col.f32.f16.f16.f32 "
        "{%0,%1,%2,%3}, {%4,%5,%6,%7}, {%8,%9}, {%0,%1,%2,%3};"
        : "+f"(c.x), "+f"(c.y), "+f"(c.z), "+f"(c.w)
        : "r"(a0), "r"(a1), "r"(a2), "r"(a3), "r"(b0), "r"(b1));
}

__device__ __forceinline__ void ldsm_x4(uint4& r, unsigned addr) {
    asm volatile("ldmatrix.sync.aligned.m8n8.x4.shared.b16 {%0,%1,%2,%3}, [%4];"
                 : "=r"(r.x), "=r"(r.y), "=r"(r.z), "=r"(r.w) : "r"(addr));
}

__device__ __forceinline__ void ldsm_x4t(uint4& r, unsigned addr) {
    asm volatile("ldmatrix.sync.aligned.m8n8.x4.trans.shared.b16 {%0,%1,%2,%3}, [%4];"
                 : "=r"(r.x), "=r"(r.y), "=r"(r.z), "=r"(r.w) : "r"(addr));
}

__device__ __forceinline__ unsigned pack_f16x2(float x, float y) {
    __half2 h = __floats2half2_rn(x, y);
    return *(unsigned*)&h;
}

__device__ __forceinline__ unsigned ex2_f16x2(unsigned a) {
    unsigned r;
    asm("ex2.approx.f16x2 %0, %1;" : "=r"(r) : "r"(a));
    return r;
}

__device__ __forceinline__ float ex2_f32(float a) {
    float r;
    asm("ex2.approx.f32 %0, %1;" : "=f"(r) : "f"(a));
    return r;
}

// ---------------------------------------------------------------------------
// One launch: packs x + 4 weights to fp16, and fills the rope tables.
// ---------------------------------------------------------------------------
#define XPAIRS (ROWS * RWU)                      // 8388608
#define TOTALP (XPAIRS + 4 * WU)                 // 16777216
#define ROPE_N (SEQ * 64)                        // 262144

__global__ void packall_kernel(const float* __restrict__ x,
                               const float* __restrict__ Wq,
                               const float* __restrict__ Wk,
                               const float* __restrict__ Wv,
                               const float* __restrict__ Wo,
                               unsigned* __restrict__ xs,
                               unsigned* __restrict__ ws) {
    int p = blockIdx.x * blockDim.x + threadIdx.x;
    if (p >= TOTALP) {                 // rope-table tail
        int idx = p - TOTALP;
        if (idx < ROPE_N) {
            int s = idx >> 6, i = idx & 63;
            double invd = pow(10000.0, -((double)(2 * i)) / 128.0);
            float arg = (float)s * (float)invd;
            double sv, cv;
            sincos((double)arg, &sv, &cv);
            g_cos[idx] = (float)cv;
            g_sin[idx] = (float)sv;
        }
        return;
    }
    const float* src;
    unsigned* dst;
    int off;
    if (p < XPAIRS) {
        src = x; dst = xs; off = p;
    } else {
        int q = p - XPAIRS;
        int wsel = q >> 21;
        off = q & (WU - 1);
        src = (wsel == 0) ? Wq : (wsel == 1) ? Wk : (wsel == 2) ? Wv : Wo;
        dst = ws + wsel * WU;
    }
    float2 v = *(const float2*)&src[2 * off];
    dst[off] = pack_f16x2(v.x, v.y);
}

// ---------------------------------------------------------------------------
// GEMM C[m,n] = sum_k A[m,k]*B[n,k]. Plain fp16, ldmatrix, k64 stages.
// 128x128 CTA tile, 8 warps (2x4), warp 64x32, 3-stage cp.async ring.
// modes: 0 = fp32 C; -1 = per bx>>4: 0->Q(rope+scale), 1->K(rope), 2->V.
// ---------------------------------------------------------------------------
#define MG_P_U    4608                        // 128 rows x 36 u32
#define MG_STAGEU (2 * MG_P_U)                // 9216 u32
#define MG_SMEM_BYTES (3 * MG_STAGEU * 4)     // 110592
#define MG_KT     (DM / 64)                   // 32

__global__ __launch_bounds__(256, 2) void mgemm_h1(
        const unsigned* __restrict__ Ag, const unsigned* __restrict__ Bg,
        int modes, float* __restrict__ Cf,
        unsigned* __restrict__ Pv,
        unsigned* __restrict__ Pq, unsigned* __restrict__ Pk) {
    extern __shared__ unsigned sm[];
    const unsigned sbase = (unsigned)__cvta_generic_to_shared(sm);
    const int tid = threadIdx.x, wid = tid >> 5, lane = tid & 31;
    const int wm = wid >> 2, wn = wid & 3, g8 = lane >> 2, qd = lane & 3;
    const int bx = blockIdx.x, by = blockIdx.y;

    const int lr = tid >> 3, lc = (tid & 7) << 2;
    const unsigned* sA = Ag + (size_t)(by * 128 + lr) * RWU + lc;
    const unsigned* sB = Bg + (size_t)(bx * 128 + lr) * RWU + lc;
    const unsigned dA0 = sbase + (unsigned)(lr * 36 + lc) * 4u;
    const unsigned dB0 = dA0 + MG_P_U * 4u;

    auto load_stage = [&](unsigned bufB, int kt) {
        const unsigned* a = sA + kt * 32;
        const unsigned* b = sB + kt * 32;
#pragma unroll
        for (int l = 0; l < 4; ++l) {
            asm volatile("cp.async.cg.shared.global [%0], [%1], 16;"
                         :: "r"(dA0 + bufB + (unsigned)(l * 4608)),
                            "l"(a + (size_t)l * 32 * RWU));
            asm volatile("cp.async.cg.shared.global [%0], [%1], 16;"
                         :: "r"(dB0 + bufB + (unsigned)(l * 4608)),
                            "l"(b + (size_t)l * 32 * RWU));
        }
        asm volatile("cp.async.commit_group;");
    };

    float4 acc[4][4];
#pragma unroll
    for (int i = 0; i < 4; i++)
#pragma unroll
        for (int j = 0; j < 4; j++) acc[i][j] = make_float4(0.f, 0.f, 0.f, 0.f);

    const int lrow16 = lane & 15, lkh = lane >> 4;
    const unsigned aLd0 = sbase
        + (unsigned)(((wm * 64 + lrow16) * 36 + lkh * 4) * 4);
    const int bg = lane >> 3, brow = lane & 7;
    const unsigned bLd0 = sbase
        + (unsigned)((MG_P_U + (wn * 32 + (bg >> 1) * 8 + brow) * 36 + (bg & 1) * 4) * 4);

    auto compute = [&](unsigned so) {
#pragma unroll
        for (int ks = 0; ks < 4; ++ks) {
            uint4 af[4];
#pragma unroll
            for (int mi = 0; mi < 4; ++mi)
                ldsm_x4(af[mi], aLd0 + so + (unsigned)((mi * 576 + ks * 8) * 4));
            uint4 bf[2];
#pragma unroll
            for (int np = 0; np < 2; ++np)
                ldsm_x4(bf[np], bLd0 + so + (unsigned)((np * 576 + ks * 8) * 4));
#pragma unroll
            for (int mi = 0; mi < 4; ++mi) {
                mma_f16(acc[mi][0], af[mi].x, af[mi].y, af[mi].z, af[mi].w,
                        bf[0].x, bf[0].y);
                mma_f16(acc[mi][1], af[mi].x, af[mi].y, af[mi].z, af[mi].w,
                        bf[0].z, bf[0].w);
                mma_f16(acc[mi][2], af[mi].x, af[mi].y, af[mi].z, af[mi].w,
                        bf[1].x, bf[1].y);
                mma_f16(acc[mi][3], af[mi].x, af[mi].y, af[mi].z, af[mi].w,
                        bf[1].z, bf[1].w);
            }
        }
    };

    load_stage(0, 0);
    load_stage(MG_STAGEU * 4u, 1);
    int cs = 0, ls = 2;
#pragma unroll 1
    for (int kt = 0; kt < MG_KT; ++kt) {
        if (kt + 1 < MG_KT) asm volatile("cp.async.wait_group 1;");
        else                asm volatile("cp.async.wait_group 0;");
        __syncthreads();
        if (kt + 2 < MG_KT) {
            load_stage((unsigned)(ls * MG_STAGEU) * 4u, kt + 2);
            ls = (ls == 2) ? 0 : ls + 1;
        }
        compute((unsigned)(cs * MG_STAGEU) * 4u);
        cs = (cs == 2) ? 0 : cs + 1;
    }

    int mode, bxl;
    if (modes >= 0) { mode = modes; bxl = bx; }
    else { int r = bx >> 4; mode = (r == 0) ? 2 : (r == 1 ? 3 : 1); bxl = bx & 15; }
    const float SC = 0.08838834764831845f;   // 1/sqrt(128)

#pragma unroll
    for (int mi = 0; mi < 4; ++mi)
#pragma unroll
        for (int ni = 0; ni < 4; ++ni) {
            int r0 = by * 128 + wm * 64 + mi * 16 + g8;
            int c0 = bxl * 128 + wn * 32 + ni * 8 + 2 * qd;
            float4 v = acc[mi][ni];
            if (mode == 0) {
                *(float2*)&Cf[(size_t)r0 * DM + c0] = make_float2(v.x, v.y);
                *(float2*)&Cf[(size_t)(r0 + 8) * DM + c0] = make_float2(v.z, v.w);
            } else if (mode == 1) {        // V plain fp16 plane
                int pA = r0 * 1024 + (c0 >> 1);
                Pv[pA] = pack_f16x2(v.x, v.y);
                Pv[pA + 8192] = pack_f16x2(v.z, v.w);
            } else {                        // Q/K: rope (+scale), plain fp16
                int i = (c0 & 127) >> 1;
                int s0 = r0 & (SEQ - 1);
                float c_ = g_cos[(s0 << 6) + i], sn = g_sin[(s0 << 6) + i];
                float c1 = g_cos[((s0 + 8) << 6) + i], s1 = g_sin[((s0 + 8) << 6) + i];
                float x0 = v.x * c_ - v.y * sn, y0 = v.y * c_ + v.x * sn;
                float x1 = v.z * c1 - v.w * s1, y1 = v.w * c1 + v.z * s1;
                int pA = r0 * 1024 + (c0 >> 1);
                if (mode == 2) {
                    x0 *= SC; y0 *= SC; x1 *= SC; y1 *= SC;
                    Pq[pA] = pack_f16x2(x0, y0);
                    Pq[pA + 8192] = pack_f16x2(x1, y1);
                } else {
                    Pk[pA] = pack_f16x2(x0, y0);
                    Pk[pA + 8192] = pack_f16x2(x1, y1);
                }
            }
        }
}

// ---------------------------------------------------------------------------
// Flash attention: 128 q-rows/CTA (256 thr, 8 warps, 16 rows/warp), 64-key
// tiles, plain fp16 QK + PV. Softmax: ex2.f16x2 -> fp16 P directly; row sums
// via ones-column MMA; alpha-rescale skipped when max unchanged (warp vote).
// ---------------------------------------------------------------------------
#define FL_Q_U     (128 * 68)                 // 8704 u32
#define FLK_U      (64 * 68)
#define FLV_U      (64 * 64)
#define FL_STAGE_U (FLK_U + FLV_U)            // 8448 u32
#define FL_SMEM_BYTES ((FL_Q_U + 2 * FL_STAGE_U) * 4)   // 102400

#define ONES_F16X2 0x3C003C00u

__global__ __launch_bounds__(256, 2) void flash_mma(const unsigned* __restrict__ qs1,
                                                    const unsigned* __restrict__ ks1,
                                                    const unsigned* __restrict__ v1,
                                                    unsigned* __restrict__ As1) {
    extern __shared__ unsigned su[];
    const unsigned sb  = (unsigned)__cvta_generic_to_shared(su);
    const unsigned QsB = sb;
    const unsigned St0 = sb + FL_Q_U * 4;

    const int tid = threadIdx.x, lane = tid & 31, w = tid >> 5;
    const int gr = lane >> 2, q4 = lane & 3;
    const int qi = (int)gridDim.x - 1 - (int)blockIdx.x;   // longest first
    const int bh = blockIdx.y;
    const int b = bh >> 4, h = bh & 15;
    const size_t qrow0 = (size_t)(b * SEQ + qi * 128);
    const int ktmax = 2 * qi + 1;
    const float L2E = 1.4426950408889634f;

    // Q tile
#pragma unroll
    for (int it = 0; it < 8; ++it) {
        int c = tid + it * 256;
        int r = c >> 4, ch = c & 15;
        const unsigned* src = qs1 + (qrow0 + r) * 1024 + h * 64 + ch * 4;
        unsigned dst = QsB + (unsigned)(r * 68 + ch * 4) * 4u;
        asm volatile("cp.async.cg.shared.global [%0], [%1], 16;" :: "r"(dst), "l"(src));
    }
    asm volatile("cp.async.commit_group;");

    auto load_kv = [&](int s, int kt) {
        const size_t krow0 = (size_t)(b * SEQ + kt * 64);
        const unsigned KB = St0 + (unsigned)(s * FL_STAGE_U) * 4u;
        const unsigned VB = KB + FLK_U * 4u;
#pragma unroll
        for (int it = 0; it < 4; ++it) {
            int c = tid + it * 256;
            int r = c >> 4, ch = c & 15;
            const unsigned* src = ks1 + (krow0 + r) * 1024 + h * 64 + ch * 4;
            asm volatile("cp.async.cg.shared.global [%0], [%1], 16;"
                         :: "r"(KB + (unsigned)(r * 68 + ch * 4) * 4u), "l"(src));
        }
#pragma unroll
        for (int it = 0; it < 4; ++it) {
            int c = tid + it * 256;
            int s_ = c >> 4, cb = c & 15;
            unsigned soff = (unsigned)(s_ * 64 + ((cb ^ (s_ & 7)) << 2)) * 4u;
            const unsigned* src = v1 + (krow0 + s_) * 1024 + h * 64 + cb * 4;
            asm volatile("cp.async.cg.shared.global [%0], [%1], 16;"
                         :: "r"(VB + soff), "l"(src));
        }
        asm volatile("cp.async.commit_group;");
    };

    load_kv(0, 0);

    const int lrow16 = lane & 15, lkh = lane >> 4;
    const unsigned qLd0 = QsB + (unsigned)(((w * 16 + lrow16) * 68 + lkh * 4) * 4);
    const int bg = lane >> 3, brow = lane & 7;
    const unsigned kLdLane = (unsigned)((((bg >> 1) * 8 + brow) * 68 + (bg & 1) * 4) * 4);
    const int mgrp = lane >> 3, lr2 = lane & 7;

    float4 O[16];
#pragma unroll
    for (int j = 0; j < 16; ++j) O[j] = make_float4(0.f, 0.f, 0.f, 0.f);
    float4 Osum = make_float4(0.f, 0.f, 0.f, 0.f);
    float m0 = -INFINITY, m1 = -INFINITY;

    for (int kt = 0; kt <= ktmax; ++kt) {
        if (kt + 1 <= ktmax) {
            load_kv((kt + 1) & 1, kt + 1);
            asm volatile("cp.async.wait_group 1;");
        } else {
            asm volatile("cp.async.wait_group 0;");
        }
        __syncthreads();

        const int st = kt & 1;
        const unsigned KBb = St0 + (unsigned)(st * FL_STAGE_U) * 4u;
        const unsigned VB = KBb + FLK_U * 4u;

        float4 s4[8];
#pragma unroll
        for (int nt = 0; nt < 8; ++nt) s4[nt] = make_float4(0.f, 0.f, 0.f, 0.f);

#pragma unroll
        for (int t = 0; t < 8; ++t) {
            uint4 aq;
            ldsm_x4(aq, qLd0 + (unsigned)(t * 32));
            uint4 kf[4];
#pragma unroll
            for (int p = 0; p < 4; ++p)
                ldsm_x4(kf[p], KBb + kLdLane + (unsigned)(p * 4352 + t * 32));
#pragma unroll
            for (int p = 0; p < 4; ++p) {
                mma_f16(s4[2 * p],     aq.x, aq.y, aq.z, aq.w, kf[p].x, kf[p].y);
                mma_f16(s4[2 * p + 1], aq.x, aq.y, aq.z, aq.w, kf[p].z, kf[p].w);
            }
        }

        if (kt >= 2 * qi) {
            int off = (kt - 2 * qi) * 64;
            int r0 = w * 16 + gr, r1 = r0 + 8;
#pragma unroll
            for (int nt = 0; nt < 8; ++nt) {
                int c0 = nt * 8 + 2 * q4 + off;
                if (c0 > r0)     s4[nt].x = -INFINITY;
                if (c0 + 1 > r0) s4[nt].y = -INFINITY;
                if (c0 > r1)     s4[nt].z = -INFINITY;
                if (c0 + 1 > r1) s4[nt].w = -INFINITY;
            }
        }

        float mx0 = -INFINITY, mx1 = -INFINITY;
#pragma unroll
        for (int nt = 0; nt < 8; ++nt) {
            mx0 = fmaxf(mx0, fmaxf(s4[nt].x, s4[nt].y));
            mx1 = fmaxf(mx1, fmaxf(s4[nt].z, s4[nt].w));
        }
        mx0 = fmaxf(mx0, __shfl_xor_sync(0xffffffffu, mx0, 1));
        mx0 = fmaxf(mx0, __shfl_xor_sync(0xffffffffu, mx0, 2));
        mx1 = fmaxf(mx1, __shfl_xor_sync(0xffffffffu, mx1, 1));
        mx1 = fmaxf(mx1, __shfl_xor_sync(0xffffffffu, mx1, 2));
        float nm0 = fmaxf(m0, mx0), nm1 = fmaxf(m1, mx1);
        float al0 = ex2_f32((m0 - nm0) * L2E), al1 = ex2_f32((m1 - nm1) * L2E);
        m0 = nm0; m1 = nm1;

        unsigned need = __ballot_sync(0xffffffffu, (al0 < 1.f) | (al1 < 1.f));
        if (need) {
#pragma unroll
            for (int j = 0; j < 16; ++j) {
                O[j].x *= al0; O[j].y *= al0; O[j].z *= al1; O[j].w *= al1;
            }
            Osum.x *= al0; Osum.y *= al0; Osum.z *= al1; Osum.w *= al1;
        }

        const float nmL0 = nm0 * L2E, nmL1 = nm1 * L2E;
        unsigned phi[16];
#pragma unroll
        for (int nt = 0; nt < 8; ++nt) {
            unsigned lo = pack_f16x2(fmaf(s4[nt].x, L2E, -nmL0),
                                     fmaf(s4[nt].y, L2E, -nmL0));
            unsigned hi = pack_f16x2(fmaf(s4[nt].z, L2E, -nmL1),
                                     fmaf(s4[nt].w, L2E, -nmL1));
            phi[2 * nt]     = ex2_f16x2(lo);
            phi[2 * nt + 1] = ex2_f16x2(hi);
        }

#pragma unroll
        for (int t2 = 0; t2 < 4; ++t2) {
            unsigned pa0 = phi[4 * t2], pa1 = phi[4 * t2 + 1];
            unsigned pa2 = phi[4 * t2 + 2], pa3 = phi[4 * t2 + 3];
            const int srow = 16 * t2 + ((mgrp & 1) << 3) + lr2;
#pragma unroll
            for (int nh = 0; nh < 2; ++nh) {
                uint4 vf[4];
#pragma unroll
                for (int nb = 0; nb < 4; ++nb) {
                    int cb = 2 * (4 * nh + nb) + (mgrp >> 1);
                    unsigned off = (unsigned)(srow * 64 + ((cb ^ (srow & 7)) << 2)) * 4u;
                    ldsm_x4t(vf[nb], VB + off);
                }
#pragma unroll
                for (int nb = 0; nb < 4; ++nb) {
                    int j = 2 * (4 * nh + nb);
                    mma_f16(O[j],     pa0, pa1, pa2, pa3, vf[nb].x, vf[nb].y);
                    mma_f16(O[j + 1], pa0, pa1, pa2, pa3, vf[nb].z, vf[nb].w);
                }
            }
            mma_f16(Osum, pa0, pa1, pa2, pa3, ONES_F16X2, ONES_F16X2);
        }
        __syncthreads();
    }

    float inv0 = 1.0f / Osum.x, inv1 = 1.0f / Osum.z;
    size_t p0 = (qrow0 + w * 16 + gr) * RWU + h * 64;
    size_t p1 = p0 + (size_t)8 * RWU;
#pragma unroll
    for (int j = 0; j < 16; ++j) {
        int pc = j * 4 + q4;
        As1[p0 + pc] = pack_f16x2(O[j].x * inv0, O[j].y * inv0);
        As1[p1 + pc] = pack_f16x2(O[j].z * inv1, O[j].w * inv1);
    }
}

// ---------------------------------------------------------------------------
extern "C" void kernel_launch(void* const* d_in, const int* in_sizes, int n_in,
                              void* d_out, int out_size) {
    const float* x  = (const float*)d_in[0];
    const float* Wq = (const float*)d_in[1];
    const float* Wk = (const float*)d_in[2];
    const float* Wv = (const float*)d_in[3];
    const float* Wo = (const float*)d_in[4];
    float* out = (float*)d_out;

    unsigned *xs, *as, *ws, *v1, *ks1, *qs1;
    cudaGetSymbolAddress((void**)&xs, g_xs);
    cudaGetSymbolAddress((void**)&as, g_as);
    cudaGetSymbolAddress((void**)&ws, g_ws);
    cudaGetSymbolAddress((void**)&v1, g_v1);
    cudaGetSymbolAddress((void**)&ks1, g_ks1);
    cudaGetSymbolAddress((void**)&qs1, g_qs1);

    // pack x + weights + rope tables in one launch
    packall_kernel<<<(TOTALP + ROPE_N) / 256, 256>>>(x, Wq, Wk, Wv, Wo, xs, ws);

    cudaFuncSetAttribute(mgemm_h1, cudaFuncAttributeMaxDynamicSharedMemorySize,
                         MG_SMEM_BYTES);
    // QKV mega-GEMM: bx 0-15 -> Q, 16-31 -> K, 32-47 -> V
    mgemm_h1<<<dim3(48, 64), 256, MG_SMEM_BYTES>>>(xs, ws, -1, nullptr,
                                                   v1, qs1, ks1);

    cudaFuncSetAttribute(flash_mma, cudaFuncAttributeMaxDynamicSharedMemorySize,
                         FL_SMEM_BYTES);
    flash_mma<<<dim3(SEQ / 128, BATCH * NH), 256, FL_SMEM_BYTES>>>(
        qs1, ks1, v1, as);

    mgemm_h1<<<dim3(16, 64), 256, MG_SMEM_BYTES>>>(as, ws + 3 * WU, 0, out,
                                                   nullptr, nullptr, nullptr);
}